// round 9
// baseline (speedup 1.0000x reference)
#include <cuda_runtime.h>
#include <cuda_fp16.h>

#define BB      16
#define CINW    128
#define COUTW   128
#define LPIX    4096
#define KTAP    9
#define XT_ROWS 4352            // 128 zero-pad + 4096 + 128 zero-pad
#define TILE_N  32
#define NTILES  128             // 4096/32

// smem stage: K=128 halfs per row = 256B + 16B pad = 272B rows (16B-aligned,
// row stride mod 128 = 16 -> 8 consecutive rows hit 8 distinct banks: conflict-free ldmatrix)
#define ROWB    272
#define A_ROWS  128
#define B_ROWS  32
#define OFF_A   0
#define A_BYTES (A_ROWS * ROWB)          // 34816
#define OFF_B   A_BYTES
#define B_BYTES (B_ROWS * ROWB)          // 8704
#define STAGE_BYTES (A_BYTES + B_BYTES)  // 43520
#define SM_MASK 0                        // 9*32 u32 = 1152
#define SM_BUF  1280
#define SMEM_TOTAL (SM_BUF + 2 * STAGE_BYTES)   // 88320 -> 2 CTAs/SM

// ---- global scratch (__device__ arrays: allocation-free rule) ----
__device__ __align__(16) __half g_x[(size_t)BB * XT_ROWS * CINW];   // fp16 x, transposed+padded
__device__ __align__(16) __half g_aw[KTAP * 128 * 128];             // [k][o][cin] fp16 w
__device__ __align__(16) float  g_mterm[(size_t)COUTW * LPIX];

// ================= PTX helpers (baseline ISA) =================
__device__ __forceinline__ unsigned smem_u32(const void* p) {
    unsigned a;
    asm("{ .reg .u64 t; cvta.to.shared.u64 t, %1; cvt.u32.u64 %0, t; }" : "=r"(a) : "l"(p));
    return a;
}
__device__ __forceinline__ void cp16(unsigned dst, const void* src) {
    asm volatile("cp.async.cg.shared.global [%0], [%1], 16;" :: "r"(dst), "l"(src) : "memory");
}
__device__ __forceinline__ void cp_commit() {
    asm volatile("cp.async.commit_group;" ::: "memory");
}
template <int N> __device__ __forceinline__ void cp_wait() {
    asm volatile("cp.async.wait_group %0;" :: "n"(N) : "memory");
}
__device__ __forceinline__ void ldsm4(unsigned* r, unsigned addr) {
    asm volatile("ldmatrix.sync.aligned.m8n8.x4.shared.b16 {%0,%1,%2,%3}, [%4];"
                 : "=r"(r[0]), "=r"(r[1]), "=r"(r[2]), "=r"(r[3]) : "r"(addr));
}
__device__ __forceinline__ void mma16816(float* c, const unsigned* a,
                                         unsigned b0, unsigned b1) {
    asm volatile(
        "mma.sync.aligned.m16n8k16.row.col.f32.f16.f16.f32 "
        "{%0,%1,%2,%3}, {%4,%5,%6,%7}, {%8,%9}, {%0,%1,%2,%3};"
        : "+f"(c[0]), "+f"(c[1]), "+f"(c[2]), "+f"(c[3])
        : "r"(a[0]), "r"(a[1]), "r"(a[2]), "r"(a[3]), "r"(b0), "r"(b1));
}

// ================= fused prep kernel (one launch, 4 disjoint ranges) =================
#define PX_BLKS  8192           // transpose: 128 lg x 4 cg x 16 b
#define PAD_BLKS 256            // 16*256*16 uint4 / 256
#define PA_BLKS  576            // 147456 / 256
#define PM_BLKS  2048           // 524288 / 256

__global__ void prep_all_kernel(const float* __restrict__ x,
                                const float* __restrict__ w,
                                const float* __restrict__ mask,
                                const float* __restrict__ mw,
                                const float* __restrict__ bias) {
    __shared__ float sm[32][33];
    int bx = blockIdx.x;
    int tid = threadIdx.x;

    if (bx < PX_BLKS) {
        // ---- x[b][c][l] fp32 -> x_t[b][128+l][c] fp16 via smem transpose ----
        int b = bx >> 9, cg = (bx >> 7) & 3, lg = bx & 127;
        int lr = tid & 31, cr = tid >> 5;
        #pragma unroll
        for (int r = 0; r < 4; r++) {
            int c = cg * 32 + cr + r * 8;
            sm[cr + r * 8][lr] = x[((size_t)(b * CINW + c)) * LPIX + lg * 32 + lr];
        }
        __syncthreads();
        #pragma unroll
        for (int r = 0; r < 4; r++) {
            int lrow = cr + r * 8;
            size_t o = ((size_t)b * XT_ROWS + 128 + lg * 32 + lrow) * CINW + cg * 32 + lr;
            g_x[o] = __float2half_rn(sm[lr][lrow]);
        }
    } else if (bx < PX_BLKS + PAD_BLKS) {
        // ---- zero the 128-row pads ----
        int t = (bx - PX_BLKS) * 256 + tid;       // 16*256*16 uint4
        int c16 = t & 15;
        int pr = (t >> 4) & 255;
        int b = t >> 12;
        int row = (pr < 128) ? pr : (pr + 4096);
        *(uint4*)&g_x[((size_t)b * XT_ROWS + row) * CINW + c16 * 8] = make_uint4(0, 0, 0, 0);
    } else if (bx < PX_BLKS + PAD_BLKS + PA_BLKS) {
        // ---- weight[o][cin][k] -> g_aw[k][o][cin] fp16 ----
        int idx = (bx - PX_BLKS - PAD_BLKS) * 256 + tid;
        if (idx < COUTW * CINW * KTAP) {
            int k = idx % KTAP;
            int cin = (idx / KTAP) % CINW;
            int o = idx / (KTAP * CINW);
            g_aw[((size_t)k * 128 + o) * 128 + cin] = __float2half_rn(w[idx]);
        }
    } else {
        // ---- mterm[o][l] = bias[o] + sum_k mw[o][k]*mask[k][l] ----
        int idx = (bx - PX_BLKS - PAD_BLKS - PA_BLKS) * 256 + tid;
        if (idx < COUTW * LPIX) {
            int o = idx >> 12, l = idx & 4095;
            float s = bias[o];
            #pragma unroll
            for (int k = 0; k < KTAP; k++)
                s += mw[o * KTAP + k] * mask[k * LPIX + l];
            g_mterm[idx] = s;
        }
    }
}

// ================= main tensor-core kernel =================
__global__ void __launch_bounds__(256, 2)
lmconv_mma_kernel(const float* __restrict__ mask, float* __restrict__ out) {
    extern __shared__ char smem[];
    unsigned sb = smem_u32(smem);
    const int tid = threadIdx.x, wid = tid >> 5, lane = tid & 31;
    const int b = blockIdx.y, l0 = blockIdx.x * TILE_N;
    const int wm = wid;                      // 8 M-warps x 1 N-warp: warp tile 16M x 32N

    unsigned* mS = (unsigned*)(smem + SM_MASK);

    // per-tile mask select words (w-edge wrap folded in)
    // NOTE: 288 words > 256 threads -> strided loop (R8 bug: guard dropped tap 8)
    for (int j = tid; j < KTAP * TILE_N; j += 256) {
        int k = j >> 5, n = j & 31;
        int l = l0 + n;
        float mv = mask[k * LPIX + l];
        int dx = k % 3 - 1;
        bool m = (mv != 0.0f);
        if (dx == 1  && (l & 63) == 63) m = false;
        if (dx == -1 && (l & 63) == 0)  m = false;
        mS[j] = m ? 0xFFFFFFFFu : 0u;
    }

    // ---- async staging: pure cp.async (mask applied in regs after ldmatrix) ----
    auto issue_stage = [&](int k) {
        unsigned buf = sb + SM_BUF + (unsigned)((k & 1) * STAGE_BYTES);
        // A: [o][128 cin] -> padded rows
        const char* srcA = (const char*)(g_aw + (size_t)k * 128 * 128);
        #pragma unroll
        for (int j = tid; j < 2048; j += 256) {
            int o = j >> 4, c16 = j & 15;
            cp16(buf + OFF_A + o * ROWB + c16 * 16, srcA + j * 16);
        }
        // B: 32 shifted rows of transposed x
        int dlt = (k / 3 - 1) * 64 + (k % 3 - 1);
        size_t base = ((size_t)(b * XT_ROWS + 128 + l0 + dlt)) * CINW;
        #pragma unroll
        for (int j = tid; j < 512; j += 256) {
            int n = j >> 4, c16 = j & 15;
            cp16(buf + OFF_B + n * ROWB + c16 * 16,
                 g_x + base + (size_t)n * CINW + c16 * 8);
        }
        cp_commit();
    };

    float acc[4][4];
    #pragma unroll
    for (int jn = 0; jn < 4; jn++)
        #pragma unroll
        for (int q = 0; q < 4; q++) acc[jn][q] = 0.0f;

    // lane-invariant ldmatrix address parts
    const unsigned a_l = (unsigned)((wm * 16 + (lane & 15)) * ROWB + ((lane >> 4) * 16));
    const unsigned b_l = (unsigned)(((lane & 15)) * ROWB + ((lane >> 4) * 16));
    const int mrow = lane >> 2;              // fragment row within 8-row block

    issue_stage(0);
    __syncthreads();                         // mask words ready (also orders mS)

    #pragma unroll 1
    for (int k = 0; k < KTAP; k++) {
        if (k + 1 < KTAP) { issue_stage(k + 1); cp_wait<1>(); }
        else              { cp_wait<0>(); }
        __syncthreads();                     // stage k visible to all warps

        unsigned base = sb + SM_BUF + (unsigned)((k & 1) * STAGE_BYTES);

        // per-warp mask words for this tap (row-granular, fragment-mapped)
        unsigned mw0[2], mw1[2];
        #pragma unroll
        for (int nb = 0; nb < 2; nb++) {
            mw0[nb] = mS[k * TILE_N + nb * 16 + mrow];
            mw1[nb] = mS[k * TILE_N + nb * 16 + 8 + mrow];
        }

        #pragma unroll
        for (int ks = 0; ks < 8; ks++) {
            unsigned co = ks * 32;           // 16 halfs per k-step
            unsigned a[4];
            ldsm4(a, base + OFF_A + a_l + co);
            #pragma unroll
            for (int nb = 0; nb < 2; nb++) {
                unsigned bf[4];
                ldsm4(bf, base + OFF_B + b_l + nb * (16 * ROWB) + co);
                bf[0] &= mw0[nb]; bf[2] &= mw0[nb];
                bf[1] &= mw1[nb]; bf[3] &= mw1[nb];
                mma16816(acc[2 * nb + 0], a, bf[0], bf[2]);
                mma16816(acc[2 * nb + 1], a, bf[1], bf[3]);
            }
        }
        __syncthreads();                     // all reads done before buf reuse
    }

    // ---- epilogue: add mterm, store float2 ----
    #pragma unroll
    for (int jn = 0; jn < 4; jn++) {
        int row0 = wm * 16 + (lane >> 2);
        int col = jn * 8 + (lane & 3) * 2;
        int l = l0 + col;
        {
            const float2 mt = *(const float2*)&g_mterm[(size_t)row0 * LPIX + l];
            float2 v;
            v.x = acc[jn][0] + mt.x;
            v.y = acc[jn][1] + mt.y;
            *(float2*)&out[((size_t)(b * COUTW + row0)) * LPIX + l] = v;
        }
        {
            int row1 = row0 + 8;
            const float2 mt = *(const float2*)&g_mterm[(size_t)row1 * LPIX + l];
            float2 v;
            v.x = acc[jn][2] + mt.x;
            v.y = acc[jn][3] + mt.y;
            *(float2*)&out[((size_t)(b * COUTW + row1)) * LPIX + l] = v;
        }
    }
}

// ================= launch =================
extern "C" void kernel_launch(void* const* d_in, const int* in_sizes, int n_in,
                              void* d_out, int out_size) {
    const float* x    = (const float*)d_in[0];   // (16,128,64,64)
    const float* mask = (const float*)d_in[1];   // (1,9,4096)
    const float* w    = (const float*)d_in[2];   // (128,128,3,3)
    const float* mw   = (const float*)d_in[3];   // (128,3,3)
    const float* bias = (const float*)d_in[4];   // (128,)
    float* out = (float*)d_out;                  // (16,128,64,64)

    cudaFuncSetAttribute(lmconv_mma_kernel,
                         cudaFuncAttributeMaxDynamicSharedMemorySize, SMEM_TOTAL);

    prep_all_kernel<<<PX_BLKS + PAD_BLKS + PA_BLKS + PM_BLKS, 256>>>(x, w, mask, mw, bias);

    lmconv_mma_kernel<<<dim3(NTILES, BB), 256, SMEM_TOTAL>>>(mask, out);
}

// round 10
// speedup vs baseline: 1.3808x; 1.3808x over previous
#include <cuda_runtime.h>
#include <cuda_fp16.h>

#define BB      16
#define CINW    128
#define COUTW   128
#define LPIX    4096
#define KTAP    9
#define XT_ROWS 4352            // 128 zero-pad + 4096 + 128 zero-pad
#define TILE_N  128
#define NTILES  32              // 4096/128

// smem stage: rows padded to 72 halfs (144B = 16*9) -> 16B-aligned, conflict-free ldmatrix
#define ROWB    144
#define TILEB   (128 * ROWB)    // 18432
#define OFF_A   0
#define OFF_B   (1 * TILEB)
#define STAGE_BYTES (2 * TILEB) // 36864
#define SM_MASK 0               // 9*128 u32 = 4608
#define SM_BUF  4608
#define SMEM_TOTAL (SM_BUF + 2 * STAGE_BYTES)   // 78336 -> 2 CTAs/SM

// ---- global scratch (__device__ arrays: allocation-free rule) ----
__device__ __align__(16) __half g_x[(size_t)BB * XT_ROWS * CINW];   // fp16 x, transposed+padded
__device__ __align__(16) __half g_aw[KTAP * 2 * 128 * 64];          // [(k,ch)][o][c] fp16 w
__device__ __align__(16) float  g_mterm[(size_t)COUTW * LPIX];

// ================= PTX helpers (baseline ISA) =================
__device__ __forceinline__ unsigned smem_u32(const void* p) {
    unsigned a;
    asm("{ .reg .u64 t; cvta.to.shared.u64 t, %1; cvt.u32.u64 %0, t; }" : "=r"(a) : "l"(p));
    return a;
}
__device__ __forceinline__ void cp16(unsigned dst, const void* src) {
    asm volatile("cp.async.cg.shared.global [%0], [%1], 16;" :: "r"(dst), "l"(src) : "memory");
}
__device__ __forceinline__ void cp_commit() {
    asm volatile("cp.async.commit_group;" ::: "memory");
}
template <int N> __device__ __forceinline__ void cp_wait() {
    asm volatile("cp.async.wait_group %0;" :: "n"(N) : "memory");
}
__device__ __forceinline__ void ldsm4(unsigned* r, unsigned addr) {
    asm volatile("ldmatrix.sync.aligned.m8n8.x4.shared.b16 {%0,%1,%2,%3}, [%4];"
                 : "=r"(r[0]), "=r"(r[1]), "=r"(r[2]), "=r"(r[3]) : "r"(addr));
}
__device__ __forceinline__ void mma16816(float* c, const unsigned* a,
                                         unsigned b0, unsigned b1) {
    asm volatile(
        "mma.sync.aligned.m16n8k16.row.col.f32.f16.f16.f32 "
        "{%0,%1,%2,%3}, {%4,%5,%6,%7}, {%8,%9}, {%0,%1,%2,%3};"
        : "+f"(c[0]), "+f"(c[1]), "+f"(c[2]), "+f"(c[3])
        : "r"(a[0]), "r"(a[1]), "r"(a[2]), "r"(a[3]), "r"(b0), "r"(b1));
}

// ================= fused prep kernel (one launch, 4 disjoint ranges) =================
#define PX_BLKS  8192           // transpose: 128 lg x 4 cg x 16 b
#define PAD_BLKS 256            // 16*256*16 uint4 / 256
#define PA_BLKS  576            // 147456 / 256
#define PM_BLKS  2048           // 524288 / 256

__global__ void prep_all_kernel(const float* __restrict__ x,
                                const float* __restrict__ w,
                                const float* __restrict__ mask,
                                const float* __restrict__ mw,
                                const float* __restrict__ bias) {
    __shared__ float sm[32][33];
    int bx = blockIdx.x;
    int tid = threadIdx.x;

    if (bx < PX_BLKS) {
        // ---- x[b][c][l] fp32 -> x_t[b][128+l][c] fp16 via smem transpose ----
        int b = bx >> 9, cg = (bx >> 7) & 3, lg = bx & 127;
        int lr = tid & 31, cr = tid >> 5;
        #pragma unroll
        for (int r = 0; r < 4; r++) {
            int c = cg * 32 + cr + r * 8;
            sm[cr + r * 8][lr] = x[((size_t)(b * CINW + c)) * LPIX + lg * 32 + lr];
        }
        __syncthreads();
        #pragma unroll
        for (int r = 0; r < 4; r++) {
            int lrow = cr + r * 8;
            size_t o = ((size_t)b * XT_ROWS + 128 + lg * 32 + lrow) * CINW + cg * 32 + lr;
            g_x[o] = __float2half_rn(sm[lr][lrow]);
        }
    } else if (bx < PX_BLKS + PAD_BLKS) {
        // ---- zero the 128-row pads ----
        int t = (bx - PX_BLKS) * 256 + tid;       // 16*256*16 uint4
        int c16 = t & 15;
        int pr = (t >> 4) & 255;
        int b = t >> 12;
        int row = (pr < 128) ? pr : (pr + 4096);
        *(uint4*)&g_x[((size_t)b * XT_ROWS + row) * CINW + c16 * 8] = make_uint4(0, 0, 0, 0);
    } else if (bx < PX_BLKS + PAD_BLKS + PA_BLKS) {
        // ---- weight[o][cin][k] -> g_aw[(k*2+ch)][o][c] fp16 ----
        int idx = (bx - PX_BLKS - PAD_BLKS) * 256 + tid;
        if (idx < COUTW * CINW * KTAP) {
            int k = idx % KTAP;
            int cin = (idx / KTAP) % CINW;
            int o = idx / (KTAP * CINW);
            int ch = cin >> 6, c = cin & 63;
            g_aw[((size_t)(k * 2 + ch) * 128 + o) * 64 + c] = __float2half_rn(w[idx]);
        }
    } else {
        // ---- mterm[o][l] = bias[o] + sum_k mw[o][k]*mask[k][l] ----
        int idx = (bx - PX_BLKS - PAD_BLKS - PA_BLKS) * 256 + tid;
        if (idx < COUTW * LPIX) {
            int o = idx >> 12, l = idx & 4095;
            float s = bias[o];
            #pragma unroll
            for (int k = 0; k < KTAP; k++)
                s += mw[o * KTAP + k] * mask[k * LPIX + l];
            g_mterm[idx] = s;
        }
    }
}

// ================= main tensor-core kernel =================
__global__ void __launch_bounds__(256, 2)
lmconv_mma_kernel(const float* __restrict__ mask, float* __restrict__ out) {
    extern __shared__ char smem[];
    unsigned sb = smem_u32(smem);
    const int tid = threadIdx.x, wid = tid >> 5, lane = tid & 31;
    const int b = blockIdx.y, l0 = blockIdx.x * TILE_N;
    const int wm = wid >> 1, wn = wid & 1;      // 4 M-warps x 2 N-warps

    unsigned* mS = (unsigned*)(smem + SM_MASK);

    // per-tile mask select words (w-edge wrap folded in)
    for (int j = tid; j < KTAP * TILE_N; j += 256) {
        int k = j >> 7, n = j & 127;
        int l = l0 + n;
        float mv = mask[k * LPIX + l];
        int dx = k % 3 - 1;
        bool m = (mv != 0.0f);
        if (dx == 1  && (l & 63) == 63) m = false;
        if (dx == -1 && (l & 63) == 0)  m = false;
        mS[j] = m ? 0xFFFFFFFFu : 0u;
    }

    // ---- async staging: pure cp.async (mask applied in regs after ldmatrix) ----
    auto issue_stage = [&](int i) {
        unsigned buf = sb + SM_BUF + (unsigned)((i & 1) * STAGE_BYTES);
        int k = i >> 1, ch = i & 1;
        // A: compact [o][64] -> padded rows
        const char* srcA = (const char*)(g_aw + (size_t)(k * 2 + ch) * 128 * 64);
        #pragma unroll
        for (int j = tid; j < 1024; j += 256) {
            int o = j >> 3, c16 = j & 7;
            cp16(buf + OFF_A + o * ROWB + c16 * 16, srcA + j * 16);
        }
        // B: shifted rows of transposed x, unmasked
        int dlt = (k / 3 - 1) * 64 + (k % 3 - 1);
        size_t base = ((size_t)(b * XT_ROWS + 128 + l0 + dlt)) * CINW + ch * 64;
        #pragma unroll
        for (int j = tid; j < 1024; j += 256) {
            int n = j >> 3, c16 = j & 7;
            cp16(buf + OFF_B + n * ROWB + c16 * 16,
                 g_x + base + (size_t)n * CINW + c16 * 8);
        }
        cp_commit();
    };

    float acc[2][8][4];
    #pragma unroll
    for (int im = 0; im < 2; im++)
        #pragma unroll
        for (int jn = 0; jn < 8; jn++)
            #pragma unroll
            for (int q = 0; q < 4; q++) acc[im][jn][q] = 0.0f;

    // lane-invariant ldmatrix address parts
    const unsigned a_l = (unsigned)((wm * 32 + (lane & 15)) * ROWB + ((lane >> 4) * 16));
    const unsigned b_l = (unsigned)((wn * 64 + (lane & 15)) * ROWB + ((lane >> 4) * 16));
    const int mrow = lane >> 2;                  // fragment row within 8-row block

    issue_stage(0);

    // ---- single-barrier pipeline:
    //   top of iter i: wait stage i complete (only pending group), barrier.
    //   Buffer (i+1)&1 was last read in iter i-1, and every thread passed this
    //   barrier after that compute -> safe to overwrite via cp.async now.
    #pragma unroll 1
    for (int i = 0; i < 2 * KTAP; i++) {
        cp_wait<0>();
        __syncthreads();
        if (i + 1 < 2 * KTAP) issue_stage(i + 1);

        unsigned base = sb + SM_BUF + (unsigned)((i & 1) * STAGE_BYTES);
        const int k = i >> 1;

        // per-warp mask words for this tap (row-granular, fragment-mapped)
        unsigned mw0[4], mw1[4];
        #pragma unroll
        for (int nb = 0; nb < 4; nb++) {
            mw0[nb] = mS[k * TILE_N + wn * 64 + nb * 16 + mrow];
            mw1[nb] = mS[k * TILE_N + wn * 64 + nb * 16 + 8 + mrow];
        }

        #pragma unroll
        for (int ks = 0; ks < 4; ks++) {
            unsigned co = ks * 32;               // 16 halfs per k-step
            unsigned a[2][4];
            ldsm4(a[0], base + OFF_A + a_l + co);
            ldsm4(a[1], base + OFF_A + a_l + 16 * ROWB + co);
            #pragma unroll
            for (int nb = 0; nb < 4; nb++) {
                unsigned bf[4];
                ldsm4(bf, base + OFF_B + b_l + nb * (16 * ROWB) + co);
                bf[0] &= mw0[nb]; bf[2] &= mw0[nb];
                bf[1] &= mw1[nb]; bf[3] &= mw1[nb];
                #pragma unroll
                for (int im = 0; im < 2; im++) {
                    mma16816(acc[im][2 * nb + 0], a[im], bf[0], bf[2]);
                    mma16816(acc[im][2 * nb + 1], a[im], bf[1], bf[3]);
                }
            }
        }
    }

    // ---- epilogue: add mterm, store float2 ----
    #pragma unroll
    for (int im = 0; im < 2; im++) {
        #pragma unroll
        for (int jn = 0; jn < 8; jn++) {
            int row0 = wm * 32 + im * 16 + (lane >> 2);
            int col = wn * 64 + jn * 8 + (lane & 3) * 2;
            int l = l0 + col;
            {
                const float2 mt = *(const float2*)&g_mterm[(size_t)row0 * LPIX + l];
                float2 v;
                v.x = acc[im][jn][0] + mt.x;
                v.y = acc[im][jn][1] + mt.y;
                *(float2*)&out[((size_t)(b * COUTW + row0)) * LPIX + l] = v;
            }
            {
                int row1 = row0 + 8;
                const float2 mt = *(const float2*)&g_mterm[(size_t)row1 * LPIX + l];
                float2 v;
                v.x = acc[im][jn][2] + mt.x;
                v.y = acc[im][jn][3] + mt.y;
                *(float2*)&out[((size_t)(b * COUTW + row1)) * LPIX + l] = v;
            }
        }
    }
}

// ================= launch =================
extern "C" void kernel_launch(void* const* d_in, const int* in_sizes, int n_in,
                              void* d_out, int out_size) {
    const float* x    = (const float*)d_in[0];   // (16,128,64,64)
    const float* mask = (const float*)d_in[1];   // (1,9,4096)
    const float* w    = (const float*)d_in[2];   // (128,128,3,3)
    const float* mw   = (const float*)d_in[3];   // (128,3,3)
    const float* bias = (const float*)d_in[4];   // (128,)
    float* out = (float*)d_out;                  // (16,128,64,64)

    cudaFuncSetAttribute(lmconv_mma_kernel,
                         cudaFuncAttributeMaxDynamicSharedMemorySize, SMEM_TOTAL);

    prep_all_kernel<<<PX_BLKS + PAD_BLKS + PA_BLKS + PM_BLKS, 256>>>(x, w, mask, mw, bias);

    lmconv_mma_kernel<<<dim3(NTILES, BB), 256, SMEM_TOTAL>>>(mask, out);
}